// round 1
// baseline (speedup 1.0000x reference)
#include <cuda_runtime.h>

// Problem constants
#define NG 4        // bands (G)
#define NB 128      // batch (B)
#define NNODE 30    // nodes (N)
#define NF 5000     // features (F)
#define NC 10       // out channels (C)
#define ROWS_G (NB*NNODE)   // 3840 rows per (mod,g)

// ---------------- device scratch (no allocations allowed) ----------------
__device__ float g_h[3 * NG * ROWS_G * NC];        // h for eeg/emg/cmc: 460800 floats
__device__ float g_fused[NG * NB * NNODE * NC];    // fused modality features

// ---------------- f32x2 packed-FMA helpers (sm_103a) ----------------
__device__ __forceinline__ unsigned long long pack2(float a, float b) {
    unsigned long long r;
    unsigned x = __float_as_uint(a), y = __float_as_uint(b);
    asm("mov.b64 %0, {%1, %2};" : "=l"(r) : "r"(x), "r"(y));
    return r;
}
__device__ __forceinline__ void unpack2(unsigned long long v, float& lo, float& hi) {
    unsigned x, y;
    asm("mov.b64 {%0, %1}, %2;" : "=r"(x), "=r"(y) : "l"(v));
    lo = __uint_as_float(x); hi = __uint_as_float(y);
}
__device__ __forceinline__ void ffma2(unsigned long long& d,
                                      unsigned long long a, unsigned long long b) {
    asm("fma.rn.f32x2 %0, %1, %2, %0;" : "+l"(d) : "l"(a), "l"(b));
}
__device__ __forceinline__ unsigned long long add2(unsigned long long a,
                                                   unsigned long long b) {
    unsigned long long d;
    asm("add.rn.f32x2 %0, %1, %2;" : "=l"(d) : "l"(a), "l"(b));
    return d;
}

// =====================================================================
// Kernel 1: h[mod,g,row,c] = sum_k x[mod][g,row,k] * W[mod][g,k,c]
// Grid: 3 mods * 4 g * 120 row-blocks = 1440 blocks, 256 threads.
// Block covers 32 rows (4 rows per warp). W tile staged transposed in SMEM.
// =====================================================================
#define KT 512

__global__ __launch_bounds__(256) void k1_gemm(
    const float* __restrict__ eeg, const float* __restrict__ emg,
    const float* __restrict__ cmc,
    const float* __restrict__ Weeg, const float* __restrict__ Wemg,
    const float* __restrict__ Wcmc)
{
    __shared__ float Ws[NC][KT];

    int blk = blockIdx.x;
    int mod = blk / 480;
    int rem = blk % 480;
    int g   = rem / 120;
    int r0  = (rem % 120) * 32;

    const float* x = (mod == 0) ? eeg : ((mod == 1) ? emg : cmc);
    const float* W = ((mod == 0) ? Weeg : ((mod == 1) ? Wemg : Wcmc)) + (size_t)g * NF * NC;

    int tid  = threadIdx.x;
    int lane = tid & 31;
    int wid  = tid >> 5;

    // 4 consecutive rows for this warp, rows contiguous within g
    size_t rowg = (size_t)g * ROWS_G + r0 + wid * 4;
    const float* p0 = x + rowg * NF;
    const float* p1 = p0 + NF;
    const float* p2 = p1 + NF;
    const float* p3 = p2 + NF;

    unsigned long long a01[NC], a23[NC];
#pragma unroll
    for (int c = 0; c < NC; c++) { a01[c] = 0ull; a23[c] = 0ull; }

    for (int tile = 0; tile < 10; ++tile) {
        int kbase = tile * KT;
        int klen  = (NF - kbase < KT) ? (NF - kbase) : KT;   // 512 or 392
        int nel   = klen * NC;
        const float* Wt = W + (size_t)kbase * NC;
        for (int idx = tid; idx < nel; idx += 256) {
            Ws[idx % NC][idx / NC] = Wt[idx];
        }
        __syncthreads();

        const float* q0 = p0 + kbase;
        const float* q1 = p1 + kbase;
        const float* q2 = p2 + kbase;
        const float* q3 = p3 + kbase;

        if (klen == KT) {
#pragma unroll 4
            for (int s = 0; s < KT / 32; ++s) {
                int kl = s * 32 + lane;
                float x0 = q0[kl], x1 = q1[kl], x2 = q2[kl], x3 = q3[kl];
                unsigned long long x01 = pack2(x0, x1);
                unsigned long long x23 = pack2(x2, x3);
#pragma unroll
                for (int c = 0; c < NC; c++) {
                    float w = Ws[c][kl];
                    unsigned long long w2 = pack2(w, w);
                    ffma2(a01[c], x01, w2);
                    ffma2(a23[c], x23, w2);
                }
            }
        } else {
            for (int s = 0; s < 13; ++s) {
                int kl = s * 32 + lane;
                if (kl < klen) {
                    float x0 = q0[kl], x1 = q1[kl], x2 = q2[kl], x3 = q3[kl];
                    unsigned long long x01 = pack2(x0, x1);
                    unsigned long long x23 = pack2(x2, x3);
#pragma unroll
                    for (int c = 0; c < NC; c++) {
                        float w = Ws[c][kl];
                        unsigned long long w2 = pack2(w, w);
                        ffma2(a01[c], x01, w2);
                        ffma2(a23[c], x23, w2);
                    }
                }
            }
        }
        __syncthreads();
    }

    // cross-lane reduction (packed)
#pragma unroll
    for (int c = 0; c < NC; c++) {
        unsigned long long v = a01[c];
#pragma unroll
        for (int off = 16; off > 0; off >>= 1)
            v = add2(v, __shfl_down_sync(0xffffffffu, v, off));
        a01[c] = v;
        v = a23[c];
#pragma unroll
        for (int off = 16; off > 0; off >>= 1)
            v = add2(v, __shfl_down_sync(0xffffffffu, v, off));
        a23[c] = v;
    }

    if (lane == 0) {
        size_t outbase = ((size_t)(mod * NG + g) * ROWS_G + r0 + wid * 4) * NC;
#pragma unroll
        for (int c = 0; c < NC; c++) {
            float lo, hi;
            unpack2(a01[c], lo, hi);
            g_h[outbase + c]          = lo;
            g_h[outbase + NC + c]     = hi;
            unpack2(a23[c], lo, hi);
            g_h[outbase + 2 * NC + c] = lo;
            g_h[outbase + 3 * NC + c] = hi;
        }
    }
}

// =====================================================================
// Kernel 2: per (g,b): GAT(eeg), GAT(emg), CMC GCN, modality MoE gate
// Grid: (128, 4), 128 threads.
// =====================================================================
__global__ __launch_bounds__(128) void k2_gat(
    const float* __restrict__ wpli_eeg, const float* __restrict__ wpli_emg,
    const float* __restrict__ cmc_train,
    const float* __restrict__ a_eeg, const float* __restrict__ a_emg,
    const float* __restrict__ b_cmc,
    const float* __restrict__ g0w1, const float* __restrict__ g0b1,
    const float* __restrict__ g0w2, const float* __restrict__ g0b2)
{
    int b = blockIdx.x, g = blockIdx.y;
    int tid = threadIdx.x;

    __shared__ float hE[NNODE][NC], hM[NNODE][NC], hC[NNODE][NC];
    __shared__ float fE[NNODE][NC], fM[NNODE][NC], fC[NNODE][NC];
    __shared__ float att[NNODE][NNODE];
    __shared__ float cor[NNODE][NNODE];
    __shared__ float f1[NNODE], f2[NNODE];
    __shared__ float hg[NNODE][64];

    size_t hbE = ((size_t)(0 * NG + g) * ROWS_G + (size_t)b * NNODE) * NC;
    size_t hbM = ((size_t)(1 * NG + g) * ROWS_G + (size_t)b * NNODE) * NC;
    size_t hbC = ((size_t)(2 * NG + g) * ROWS_G + (size_t)b * NNODE) * NC;
    for (int i = tid; i < NNODE * NC; i += 128) {
        hE[i / NC][i % NC] = g_h[hbE + i];
        hM[i / NC][i % NC] = g_h[hbM + i];
        hC[i / NC][i % NC] = g_h[hbC + i];
    }
    // cmc_cor = mean over T=8 of cmc_train[t,g,:,:]
    for (int i = tid; i < NNODE * NNODE; i += 128) {
        float s = 0.f;
#pragma unroll
        for (int t = 0; t < 8; t++)
            s += cmc_train[(size_t)t * (NG * NNODE * NNODE) + (size_t)g * (NNODE * NNODE) + i];
        cor[i / NNODE][i % NNODE] = s * 0.125f;
    }
    __syncthreads();

    // CMC expert: cor @ hC + b (no activation)
    for (int idx = tid; idx < NNODE * NC; idx += 128) {
        int i = idx / NC, c = idx % NC;
        float s = 0.f;
        for (int j = 0; j < NNODE; j++) s += cor[i][j] * hC[j][c];
        fC[i][c] = s + b_cmc[g * NC + c];
    }

    // GAT experts (eeg, emg)
    for (int m = 0; m < 2; ++m) {
        const float* a   = ((m == 0) ? a_eeg : a_emg) + g * 2 * NC;
        const float* adj = ((m == 0) ? wpli_eeg : wpli_emg) + g * NNODE * NNODE;
        float (*h)[NC] = (m == 0) ? hE : hM;
        float (*f)[NC] = (m == 0) ? fE : fM;
        __syncthreads();   // h visible (m=0); att free for reuse (m=1)
        if (tid < NNODE) {
            float s1 = 0.f, s2 = 0.f;
#pragma unroll
            for (int c = 0; c < NC; c++) {
                s1 += h[tid][c] * a[c];
                s2 += h[tid][c] * a[NC + c];
            }
            f1[tid] = s1; f2[tid] = s2;
        }
        __syncthreads();
        if (tid < NNODE) {           // softmax over i, column j = tid
            int j = tid;
            float mx = -1e30f;
            for (int i = 0; i < NNODE; i++) {
                float v;
                if (adj[i * NNODE + j] > 0.f) {
                    float e = f1[i] + f2[j];
                    v = (e > 0.f) ? e : 0.1f * e;   // LeakyReLU(0.1)
                } else {
                    v = -1e12f;
                }
                att[i][j] = v;
                mx = fmaxf(mx, v);
            }
            float s = 0.f;
            for (int i = 0; i < NNODE; i++) {
                float ex = expf(att[i][j] - mx);
                att[i][j] = ex; s += ex;
            }
            float inv = 1.f / s;
            for (int i = 0; i < NNODE; i++) att[i][j] *= inv;
        }
        __syncthreads();
        for (int idx = tid; idx < NNODE * NC; idx += 128) {
            int i = idx / NC, c = idx % NC;
            float s = 0.f;
            for (int j = 0; j < NNODE; j++) s += att[i][j] * h[j][c];
            f[i][c] = fmaxf(s, 0.f);
        }
    }
    __syncthreads();

    // gating0: relu([fE,fM,fC] @ w1 + b1) @ w2 + b2 -> softmax3 -> fuse
    for (int idx = tid; idx < NNODE * 64; idx += 128) {
        int n = idx / 64, o = idx % 64;
        float s = g0b1[o];
#pragma unroll
        for (int k = 0; k < 10; k++) s += fE[n][k] * g0w1[k * 64 + o];
#pragma unroll
        for (int k = 0; k < 10; k++) s += fM[n][k] * g0w1[(10 + k) * 64 + o];
#pragma unroll
        for (int k = 0; k < 10; k++) s += fC[n][k] * g0w1[(20 + k) * 64 + o];
        hg[n][o] = fmaxf(s, 0.f);
    }
    __syncthreads();
    if (tid < NNODE) {
        int n = tid;
        float l0 = g0b2[0], l1 = g0b2[1], l2 = g0b2[2];
        for (int o = 0; o < 64; o++) {
            float v = hg[n][o];
            l0 += v * g0w2[o * 3 + 0];
            l1 += v * g0w2[o * 3 + 1];
            l2 += v * g0w2[o * 3 + 2];
        }
        float mx = fmaxf(l0, fmaxf(l1, l2));
        float e0 = expf(l0 - mx), e1 = expf(l1 - mx), e2 = expf(l2 - mx);
        float inv = 1.f / (e0 + e1 + e2);
        e0 *= inv; e1 *= inv; e2 *= inv;
        size_t ob = ((size_t)(g * NB + b) * NNODE + n) * NC;
#pragma unroll
        for (int c = 0; c < NC; c++)
            g_fused[ob + c] = e0 * fE[n][c] + e1 * fM[n][c] + e2 * fC[n][c];
    }
}

// =====================================================================
// Kernel 3: per b: band MoE gate, node pooling, MLP head + BN
// Grid: 128 blocks, 64 threads.
// =====================================================================
__global__ __launch_bounds__(64) void k3_head(
    const float* __restrict__ g1w1, const float* __restrict__ g1b1,
    const float* __restrict__ g1w2, const float* __restrict__ g1b2,
    const float* __restrict__ mlp0w, const float* __restrict__ mlp0b,
    const float* __restrict__ mlp1w, const float* __restrict__ mlp1b,
    const float* __restrict__ mlp2w, const float* __restrict__ mlp2b,
    const float* __restrict__ bng, const float* __restrict__ bnb,
    float* __restrict__ out)
{
    int b = blockIdx.x, tid = threadIdx.x;
    __shared__ float band[NNODE][40];
    __shared__ float hg[NNODE][64];
    __shared__ float gs[NNODE][4];
    __shared__ float feat[40];
    __shared__ float h1[256];
    __shared__ float h2[32];

    for (int idx = tid; idx < NNODE * 40; idx += 64) {
        int n = idx / 40, d = idx % 40, g = d / 10, c = d % 10;
        band[n][d] = g_fused[((size_t)(g * NB + b) * NNODE + n) * NC + c];
    }
    __syncthreads();

    for (int idx = tid; idx < NNODE * 64; idx += 64) {
        int n = idx / 64, o = idx % 64;
        float s = g1b1[o];
#pragma unroll
        for (int k = 0; k < 40; k++) s += band[n][k] * g1w1[k * 64 + o];
        hg[n][o] = fmaxf(s, 0.f);
    }
    __syncthreads();
    if (tid < NNODE) {
        float l[4];
#pragma unroll
        for (int e = 0; e < 4; e++) l[e] = g1b2[e];
        for (int o = 0; o < 64; o++) {
            float v = hg[tid][o];
#pragma unroll
            for (int e = 0; e < 4; e++) l[e] += v * g1w2[o * 4 + e];
        }
        float mx = fmaxf(fmaxf(l[0], l[1]), fmaxf(l[2], l[3]));
        float s = 0.f;
#pragma unroll
        for (int e = 0; e < 4; e++) { l[e] = expf(l[e] - mx); s += l[e]; }
        float inv = 1.f / s;
#pragma unroll
        for (int e = 0; e < 4; e++) gs[tid][e] = l[e] * inv;
    }
    __syncthreads();
    if (tid < 40) {
        float s = 0.f;
        for (int n = 0; n < NNODE; n++) s += band[n][tid] * gs[n][tid / 10];
        feat[tid] = s * (1.f / 30.f);
    }
    __syncthreads();
    for (int o = tid; o < 256; o += 64) {
        float s = mlp0b[o];
#pragma unroll
        for (int k = 0; k < 40; k++) s += feat[k] * mlp0w[k * 256 + o];
        h1[o] = fmaxf(s, 0.f);
    }
    __syncthreads();
    if (tid < 32) {
        float s = mlp1b[tid];
        for (int k = 0; k < 256; k++) s += h1[k] * mlp1w[k * 32 + tid];
        s = fmaxf(s, 0.f);
        h2[tid] = s * (bng[tid] * rsqrtf(1.f + 1e-5f)) + bnb[tid];
    }
    __syncthreads();
    if (tid < 4) {
        float s = mlp2b[tid];
#pragma unroll
        for (int k = 0; k < 32; k++) s += h2[k] * mlp2w[k * 4 + tid];
        out[b * 4 + tid] = s;
    }
}

// =====================================================================
extern "C" void kernel_launch(void* const* d_in, const int* in_sizes, int n_in,
                              void* d_out, int out_size)
{
    const float* eeg       = (const float*)d_in[0];
    const float* wpli_eeg  = (const float*)d_in[1];
    const float* emg       = (const float*)d_in[2];
    const float* wpli_emg  = (const float*)d_in[3];
    const float* cmc       = (const float*)d_in[4];
    const float* cmc_train = (const float*)d_in[5];
    const float* W_eeg     = (const float*)d_in[6];
    const float* a_eeg     = (const float*)d_in[7];
    const float* W_emg     = (const float*)d_in[8];
    const float* a_emg     = (const float*)d_in[9];
    const float* W_cmc     = (const float*)d_in[10];
    const float* b_cmc     = (const float*)d_in[11];
    const float* g0w1      = (const float*)d_in[12];
    const float* g0b1      = (const float*)d_in[13];
    const float* g0w2      = (const float*)d_in[14];
    const float* g0b2      = (const float*)d_in[15];
    const float* g1w1      = (const float*)d_in[16];
    const float* g1b1      = (const float*)d_in[17];
    const float* g1w2      = (const float*)d_in[18];
    const float* g1b2      = (const float*)d_in[19];
    const float* mlp0w     = (const float*)d_in[20];
    const float* mlp0b     = (const float*)d_in[21];
    const float* mlp1w     = (const float*)d_in[22];
    const float* mlp1b     = (const float*)d_in[23];
    const float* mlp2w     = (const float*)d_in[24];
    const float* mlp2b     = (const float*)d_in[25];
    const float* bng       = (const float*)d_in[26];
    const float* bnb       = (const float*)d_in[27];

    k1_gemm<<<1440, 256>>>(eeg, emg, cmc, W_eeg, W_emg, W_cmc);

    dim3 g2(NB, NG);
    k2_gat<<<g2, 128>>>(wpli_eeg, wpli_emg, cmc_train,
                        a_eeg, a_emg, b_cmc, g0w1, g0b1, g0w2, g0b2);

    k3_head<<<NB, 64>>>(g1w1, g1b1, g1w2, g1b2,
                        mlp0w, mlp0b, mlp1w, mlp1b, mlp2w, mlp2b,
                        bng, bnb, (float*)d_out);
}